// round 14
// baseline (speedup 1.0000x reference)
#include <cuda_runtime.h>
#include <cuda_fp16.h>
#include <cstdint>

// Problem dims (fixed by the dataset)
#define M_DIM 32768   // B*S
#define K_DIM 1152
#define N_DIM 1152
#define R_DIM 64
#define QMAXV 255.0f
#define RBLOCKS 2304                      // reduce grid size

// ---------------- device scratch ----------------
__device__ float2   g_blkred[RBLOCKS];    // per-block (max, min); fully rewritten each call
__device__ float    g_scale;              // published by quant block 0
__device__ __align__(16) __half g_A[(size_t)M_DIM * K_DIM];  // (q-zp): exact int in fp16
__device__ __align__(16) __half g_W[(size_t)N_DIM * K_DIM];  // merged weight in fp16

__device__ __forceinline__ uint32_t smem_u32(const void* p) {
    uint32_t a;
    asm("{ .reg .u64 t; cvta.to.shared.u64 t, %1; cvt.u32.u64 %0, t; }" : "=r"(a) : "l"(p));
    return a;
}

#define CP_ASYNC16(saddr, gptr) \
    asm volatile("cp.async.cg.shared.global [%0], [%1], 16;" :: "r"(saddr), "l"(gptr) : "memory")
#define CP_COMMIT() asm volatile("cp.async.commit_group;" ::: "memory")
#define CP_WAIT1()  asm volatile("cp.async.wait_group 1;" ::: "memory")

// ---------------- kernel: per-block min/max of x*rinv ----------------
__global__ __launch_bounds__(256)
void reduce_kernel(const float* __restrict__ x, const float* __restrict__ scales) {
    __shared__ float4 rinv4[K_DIM / 4];
    {
        float* rinv = reinterpret_cast<float*>(rinv4);
        for (int k = threadIdx.x; k < K_DIM; k += 256)
            rinv[k] = 1.0f / scales[k];
    }
    __syncthreads();

    const int total4 = (M_DIM * K_DIM) / 4;
    const float INF = __int_as_float(0x7f800000);
    float vmax = -INF, vmin = INF;
    for (int v = blockIdx.x * 256 + threadIdx.x; v < total4; v += RBLOCKS * 256) {
        float4 xv = reinterpret_cast<const float4*>(x)[v];
        float4 rv = rinv4[v % (K_DIM / 4)];
        float a = xv.x * rv.x;
        float b = xv.y * rv.y;
        float c = xv.z * rv.z;
        float d = xv.w * rv.w;
        vmax = fmaxf(vmax, fmaxf(fmaxf(a, b), fmaxf(c, d)));
        vmin = fminf(vmin, fminf(fminf(a, b), fminf(c, d)));
    }
    #pragma unroll
    for (int off = 16; off > 0; off >>= 1) {
        vmax = fmaxf(vmax, __shfl_xor_sync(0xffffffffu, vmax, off));
        vmin = fminf(vmin, __shfl_xor_sync(0xffffffffu, vmin, off));
    }
    __shared__ float smax[8], smin[8];
    int wid = threadIdx.x >> 5, lane = threadIdx.x & 31;
    if (lane == 0) { smax[wid] = vmax; smin[wid] = vmin; }
    __syncthreads();
    if (threadIdx.x == 0) {
        float bm = smax[0], bn = smin[0];
        #pragma unroll
        for (int i = 1; i < 8; i++) {
            bm = fmaxf(bm, smax[i]);
            bn = fminf(bn, smin[i]);
        }
        g_blkred[blockIdx.x] = make_float2(bm, bn);
    }
}

// ---------------- kernel: merge W = quant_w + left @ right -> fp16 (smem-tiled) ------
// grid (K_DIM/96, N_DIM/64) = (12, 18), 256 threads.
#define MKT 96
#define MNT 64
__global__ __launch_bounds__(256)
void merge_kernel(const float* __restrict__ qw,
                  const float* __restrict__ rw,
                  const float* __restrict__ lw) {
    __shared__ float lw_s[MNT][R_DIM + 4];   // 64 x 68 (pad: stride 68 mod 32 = 4)
    __shared__ float rw_s[R_DIM][MKT];       // 64 x 96

    const int k0 = blockIdx.x * MKT;
    const int n0 = blockIdx.y * MNT;
    const int tid = threadIdx.x;

    // load lw tile (64 n x 64 r), coalesced over r
    for (int i = tid; i < MNT * R_DIM; i += 256) {
        int n = i >> 6, r = i & 63;
        lw_s[n][r] = lw[(n0 + n) * R_DIM + r];
    }
    // load rw tile (64 r x 96 k), coalesced over k
    for (int i = tid; i < R_DIM * MKT; i += 256) {
        int r = i / MKT, k = i - r * MKT;
        rw_s[r][k] = rw[r * K_DIM + k0 + k];
    }
    __syncthreads();

    const int nl = tid >> 3;            // 0..31 (handles n = nl and nl+32)
    const int kl = tid & 7;             // k = kl + 8*j, j = 0..11

    float acc0[12], acc1[12];
    #pragma unroll
    for (int j = 0; j < 12; j++) {
        acc0[j] = qw[(size_t)(n0 + nl) * K_DIM + k0 + kl + 8 * j];
        acc1[j] = qw[(size_t)(n0 + nl + 32) * K_DIM + k0 + kl + 8 * j];
    }
    #pragma unroll 4
    for (int r = 0; r < R_DIM; r++) {
        float l0 = lw_s[nl][r];
        float l1 = lw_s[nl + 32][r];
        #pragma unroll
        for (int j = 0; j < 12; j++) {
            float rv = rw_s[r][kl + 8 * j];
            acc0[j] = fmaf(l0, rv, acc0[j]);
            acc1[j] = fmaf(l1, rv, acc1[j]);
        }
    }
    #pragma unroll
    for (int j = 0; j < 12; j++) {
        g_W[(size_t)(n0 + nl) * K_DIM + k0 + kl + 8 * j] = __float2half_rn(acc0[j]);
        g_W[(size_t)(n0 + nl + 32) * K_DIM + k0 + kl + 8 * j] = __float2half_rn(acc1[j]);
    }
}

// ---------------- kernel: finalize params + quantize A (fp16 output) ----------------
__global__ __launch_bounds__(256)
void quant_kernel(const float* __restrict__ x, const float* __restrict__ scales) {
    __shared__ float4 rinv4[K_DIM / 4];
    __shared__ float smax[8], smin[8];
    __shared__ float s_zp, s_rqs;

    {
        float* rinv = reinterpret_cast<float*>(rinv4);
        for (int k = threadIdx.x; k < K_DIM; k += 256)
            rinv[k] = 1.0f / scales[k];
    }

    // finalize global max/min from reduce slots
    const float INF = __int_as_float(0x7f800000);
    float vmax = -INF, vmin = INF;
    for (int i = threadIdx.x; i < RBLOCKS; i += 256) {
        float2 t = g_blkred[i];
        vmax = fmaxf(vmax, t.x);
        vmin = fminf(vmin, t.y);
    }
    #pragma unroll
    for (int off = 16; off > 0; off >>= 1) {
        vmax = fmaxf(vmax, __shfl_xor_sync(0xffffffffu, vmax, off));
        vmin = fminf(vmin, __shfl_xor_sync(0xffffffffu, vmin, off));
    }
    int wid = threadIdx.x >> 5, lane = threadIdx.x & 31;
    if (lane == 0) { smax[wid] = vmax; smin[wid] = vmin; }
    __syncthreads();
    if (threadIdx.x == 0) {
        float mx = smax[0], mn = smin[0];
        #pragma unroll
        for (int i = 1; i < 8; i++) {
            mx = fmaxf(mx, smax[i]);
            mn = fminf(mn, smin[i]);
        }
        float qs = (mx - mn) / QMAXV;
        s_zp = rintf(-mn / qs);
        s_rqs = 1.0f / qs;
        if (blockIdx.x == 0) g_scale = qs;   // publish for GEMM epilogue
    }
    __syncthreads();
    const float zp = s_zp, rqs = s_rqs;

    const int total8 = (M_DIM * K_DIM) / 8;
    const int stride = 1152 * 256;
    for (int v = blockIdx.x * 256 + threadIdx.x; v < total8; v += stride) {
        float4 x0 = reinterpret_cast<const float4*>(x)[2 * v];
        float4 x1 = reinterpret_cast<const float4*>(x)[2 * v + 1];
        int ri = (2 * v) % (K_DIM / 4);
        float4 r0 = rinv4[ri];
        float4 r1 = rinv4[ri + 1];
        float f[8];
        f[0] = x0.x * r0.x; f[1] = x0.y * r0.y;
        f[2] = x0.z * r0.z; f[3] = x0.w * r0.w;
        f[4] = x1.x * r1.x; f[5] = x1.y * r1.y;
        f[6] = x1.z * r1.z; f[7] = x1.w * r1.w;
        #pragma unroll
        for (int j = 0; j < 8; j++)
            f[j] = fminf(fmaxf(rintf(f[j] * rqs) + zp, 0.0f), QMAXV) - zp;
        __half2 p0 = __floats2half2_rn(f[0], f[1]);
        __half2 p1 = __floats2half2_rn(f[2], f[3]);
        __half2 p2 = __floats2half2_rn(f[4], f[5]);
        __half2 p3 = __floats2half2_rn(f[6], f[7]);
        uint4 u;
        u.x = *reinterpret_cast<unsigned*>(&p0);
        u.y = *reinterpret_cast<unsigned*>(&p1);
        u.z = *reinterpret_cast<unsigned*>(&p2);
        u.w = *reinterpret_cast<unsigned*>(&p3);
        reinterpret_cast<uint4*>(g_A)[v] = u;
    }
}

// ---------------- kernel: persistent fp16 mma.sync GEMM ----------------
// CTA tile 128x128, 256 threads, 8 warps as 2(M) x 4(N), warp tile 64x32.
// 296 persistent CTAs (2/SM); each processes 7-8 tiles with ONE continuous
// cp.async pipeline (no drain/refill between tiles).
#define BM 128
#define BN 128
#define BK 64
#define NSTAGES 3
#define KITERS (K_DIM / BK)             // 18
#define PADH 72
#define PADB (PADH * 2)                 // 144 bytes/row
#define TILE_B (128 * PADB)             // 18432
#define STAGE_B (2 * TILE_B)            // 36864
#define SMEM_DYN (NSTAGES * STAGE_B)    // 110592 (x2 CTAs = 221184 <= 227KB)
#define NTILES_N (N_DIM / BN)           // 9
#define NTILES   ((M_DIM / BM) * NTILES_N)   // 2304
#define NCTAS 296

__device__ __forceinline__ void ldm_x4(uint32_t* d, uint32_t addr) {
    asm volatile("ldmatrix.sync.aligned.m8n8.x4.shared.b16 {%0,%1,%2,%3}, [%4];"
                 : "=r"(d[0]), "=r"(d[1]), "=r"(d[2]), "=r"(d[3]) : "r"(addr));
}
__device__ __forceinline__ void hmma16816(float* c, const uint32_t* a, const uint32_t* b) {
    asm volatile(
        "mma.sync.aligned.m16n8k16.row.col.f32.f16.f16.f32 "
        "{%0,%1,%2,%3}, {%4,%5,%6,%7}, {%8,%9}, {%0,%1,%2,%3};\n"
        : "+f"(c[0]), "+f"(c[1]), "+f"(c[2]), "+f"(c[3])
        : "r"(a[0]), "r"(a[1]), "r"(a[2]), "r"(a[3]), "r"(b[0]), "r"(b[1]));
}

__device__ __forceinline__ void load_stage(uint32_t sA, uint32_t sB,
                                           const __half* Ag, const __half* Bg,
                                           int k0, int tid) {
    #pragma unroll
    for (int q = 0; q < 4; q++) {
        int c = q * 256 + tid;            // 0..1023
        int row = c >> 3;                 // 0..127
        int col16 = c & 7;
        uint32_t soff = (uint32_t)row * PADB + col16 * 16;
        CP_ASYNC16(sA + soff, Ag + (size_t)row * K_DIM + k0 + col16 * 8);
        CP_ASYNC16(sB + soff, Bg + (size_t)row * K_DIM + k0 + col16 * 8);
    }
}

__global__ __launch_bounds__(256, 2)
void gemm_kernel(const float* __restrict__ bias, float* __restrict__ out) {
    extern __shared__ char dsmem[];
    const uint32_t sbase = smem_u32(dsmem);

    const int tid = threadIdx.x;
    const int lane = tid & 31;
    const int warp = tid >> 5;
    const int warp_m = warp >> 2;   // 2 warp rows (64 rows each)
    const int warp_n = warp & 3;    // 4 warp cols (32 cols each)
    const int gid = lane >> 2;
    const int tig = lane & 3;
    const int cta = blockIdx.x;

    const int my_ntiles = (NTILES - cta + NCTAS - 1) / NCTAS;   // 7 or 8
    const int total_g = my_ntiles * KITERS;

    // ldmatrix per-lane address components
    const int lane15 = lane & 15;
    const int laneHiA = (lane >> 4) * 16;
    const uint32_t aLaneOff = (uint32_t)(warp_m * 64 + lane15) * PADB + laneHiA;
    const int rowB = warp_n * 32 + (lane >> 4) * 8 + (lane & 7);
    const int kaddB = ((lane >> 3) & 1) * 16;
    const uint32_t bLaneOff = (uint32_t)rowB * PADB + kaddB;

    // loader state (runs 2 stages ahead)
    int lt = cta;
    int l_k = 0;
    const __half* lA = g_A + (size_t)(lt / NTILES_N) * BM * K_DIM;
    const __half* lB = g_W + (size_t)(lt % NTILES_N) * BN * K_DIM;

    float acc[4][4][4];
    #pragma unroll
    for (int i = 0; i < 4; i++)
        #pragma unroll
        for (int j = 0; j < 4; j++)
            #pragma unroll
            for (int r = 0; r < 4; r++) acc[i][j][r] = 0.0f;

    // prologue: fill 2 stages (g = 0, 1)
    #pragma unroll
    for (int st = 0; st < NSTAGES - 1; st++) {
        const uint32_t sA = sbase + st * STAGE_B;
        load_stage(sA, sA + TILE_B, lA, lB, l_k * BK, tid);
        CP_COMMIT();
        if (++l_k == KITERS) {
            l_k = 0;
            lt += NCTAS;
            if (lt < NTILES) {
                lA = g_A + (size_t)(lt / NTILES_N) * BM * K_DIM;
                lB = g_W + (size_t)(lt % NTILES_N) * BN * K_DIM;
            }
        }
    }

    // compute-side tile state
    int ct = cta;
    int m0 = (ct / NTILES_N) * BM;
    int n0 = (ct % NTILES_N) * BN;
    int ck = 0;
    const float s = g_scale;

    for (int g = 0; g < total_g; ++g) {
        CP_WAIT1();
        __syncthreads();

        const uint32_t sA = sbase + (g % NSTAGES) * STAGE_B;
        const uint32_t sB = sA + TILE_B;

        // prefetch stage g+2 into the buffer freed at iteration g-1
        if (g + 2 < total_g) {
            const uint32_t fA = sbase + ((g + 2) % NSTAGES) * STAGE_B;
            load_stage(fA, fA + TILE_B, lA, lB, l_k * BK, tid);
            if (++l_k == KITERS) {
                l_k = 0;
                lt += NCTAS;
                if (lt < NTILES) {
                    lA = g_A + (size_t)(lt / NTILES_N) * BM * K_DIM;
                    lB = g_W + (size_t)(lt % NTILES_N) * BN * K_DIM;
                }
            }
        }
        CP_COMMIT();

        #pragma unroll
        for (int ks = 0; ks < 4; ks++) {
            uint32_t a[4][4], b[2][4];
            #pragma unroll
            for (int im = 0; im < 4; im++)
                ldm_x4(a[im], sA + aLaneOff + (uint32_t)im * 16 * PADB + ks * 32);
            #pragma unroll
            for (int j2 = 0; j2 < 2; j2++)
                ldm_x4(b[j2], sB + bLaneOff + (uint32_t)j2 * 16 * PADB + ks * 32);
            #pragma unroll
            for (int im = 0; im < 4; im++) {
                hmma16816(acc[im][0], a[im], &b[0][0]);
                hmma16816(acc[im][1], a[im], &b[0][2]);
                hmma16816(acc[im][2], a[im], &b[1][0]);
                hmma16816(acc[im][3], a[im], &b[1][2]);
            }
        }

        if (++ck == KITERS) {
            // epilogue for tile ct: out = acc * scale + bias
            ck = 0;
            #pragma unroll
            for (int im = 0; im < 4; im++) {
                int m = m0 + warp_m * 64 + im * 16 + gid;
                #pragma unroll
                for (int jn = 0; jn < 4; jn++) {
                    int n = n0 + warp_n * 32 + jn * 8 + tig * 2;
                    float b0 = bias[n], b1 = bias[n + 1];
                    float2 v0, v1;
                    v0.x = acc[im][jn][0] * s + b0;
                    v0.y = acc[im][jn][1] * s + b1;
                    v1.x = acc[im][jn][2] * s + b0;
                    v1.y = acc[im][jn][3] * s + b1;
                    *reinterpret_cast<float2*>(out + (size_t)m * N_DIM + n) = v0;
                    *reinterpret_cast<float2*>(out + (size_t)(m + 8) * N_DIM + n) = v1;
                    acc[im][jn][0] = 0.0f;
                    acc[im][jn][1] = 0.0f;
                    acc[im][jn][2] = 0.0f;
                    acc[im][jn][3] = 0.0f;
                }
            }
            ct += NCTAS;
            if (ct < NTILES) {
                m0 = (ct / NTILES_N) * BM;
                n0 = (ct % NTILES_N) * BN;
            }
        }
    }
}

// ---------------- launch ----------------
extern "C" void kernel_launch(void* const* d_in, const int* in_sizes, int n_in,
                              void* d_out, int out_size) {
    const float* x      = (const float*)d_in[0];
    const float* qw     = (const float*)d_in[1];
    const float* rw     = (const float*)d_in[2];
    const float* lw     = (const float*)d_in[3];
    const float* bias   = (const float*)d_in[4];
    const float* scales = (const float*)d_in[5];
    float* out = (float*)d_out;

    static cudaStream_t s2 = nullptr;
    static cudaEvent_t ev_fork = nullptr, ev_join = nullptr;
    static bool init_done = false;
    if (!init_done) {
        cudaFuncSetAttribute(gemm_kernel, cudaFuncAttributeMaxDynamicSharedMemorySize, SMEM_DYN);
        cudaStreamCreateWithFlags(&s2, cudaStreamNonBlocking);
        cudaEventCreateWithFlags(&ev_fork, cudaEventDisableTiming);
        cudaEventCreateWithFlags(&ev_join, cudaEventDisableTiming);
        init_done = true;
    }

    // fork: merge (independent, now cheap) on s2, overlapping reduce+quant
    cudaEventRecord(ev_fork, 0);
    cudaStreamWaitEvent(s2, ev_fork, 0);
    merge_kernel<<<dim3(K_DIM / MKT, N_DIM / MNT), 256, 0, s2>>>(qw, rw, lw);
    cudaEventRecord(ev_join, s2);

    // main chain: reduce -> quant (finalizes params) -> gemm
    reduce_kernel<<<RBLOCKS, 256>>>(x, scales);
    quant_kernel<<<1152, 256>>>(x, scales);
    cudaStreamWaitEvent(0, ev_join, 0);
    gemm_kernel<<<NCTAS, 256, SMEM_DYN>>>(bias, out);
}

// round 15
// speedup vs baseline: 1.0568x; 1.0568x over previous
#include <cuda_runtime.h>
#include <cuda_fp16.h>
#include <cstdint>

// Problem dims (fixed by the dataset)
#define M_DIM 32768   // B*S
#define K_DIM 1152
#define N_DIM 1152
#define R_DIM 64
#define QMAXV 255.0f
#define RBLOCKS 2304                      // reduce grid size

// ---------------- device scratch ----------------
__device__ float2   g_blkred[RBLOCKS];    // per-block (max, min); fully rewritten each call
__device__ float    g_scale;              // published by quant block 0
__device__ __align__(16) __half g_A[(size_t)M_DIM * K_DIM];  // (q-zp): exact int in fp16
__device__ __align__(16) __half g_W[(size_t)N_DIM * K_DIM];  // merged weight in fp16

__device__ __forceinline__ uint32_t smem_u32(const void* p) {
    uint32_t a;
    asm("{ .reg .u64 t; cvta.to.shared.u64 t, %1; cvt.u32.u64 %0, t; }" : "=r"(a) : "l"(p));
    return a;
}

#define CP_ASYNC16(saddr, gptr) \
    asm volatile("cp.async.cg.shared.global [%0], [%1], 16;" :: "r"(saddr), "l"(gptr) : "memory")
#define CP_COMMIT() asm volatile("cp.async.commit_group;" ::: "memory")
#define CP_WAIT1()  asm volatile("cp.async.wait_group 1;" ::: "memory")

// ---------------- kernel: per-block min/max of x*rinv ----------------
__global__ __launch_bounds__(256)
void reduce_kernel(const float* __restrict__ x, const float* __restrict__ scales) {
    __shared__ float4 rinv4[K_DIM / 4];
    {
        float* rinv = reinterpret_cast<float*>(rinv4);
        for (int k = threadIdx.x; k < K_DIM; k += 256)
            rinv[k] = 1.0f / scales[k];
    }
    __syncthreads();

    const int total4 = (M_DIM * K_DIM) / 4;
    const float INF = __int_as_float(0x7f800000);
    float vmax = -INF, vmin = INF;
    for (int v = blockIdx.x * 256 + threadIdx.x; v < total4; v += RBLOCKS * 256) {
        float4 xv = reinterpret_cast<const float4*>(x)[v];
        float4 rv = rinv4[v % (K_DIM / 4)];
        float a = xv.x * rv.x;
        float b = xv.y * rv.y;
        float c = xv.z * rv.z;
        float d = xv.w * rv.w;
        vmax = fmaxf(vmax, fmaxf(fmaxf(a, b), fmaxf(c, d)));
        vmin = fminf(vmin, fminf(fminf(a, b), fminf(c, d)));
    }
    #pragma unroll
    for (int off = 16; off > 0; off >>= 1) {
        vmax = fmaxf(vmax, __shfl_xor_sync(0xffffffffu, vmax, off));
        vmin = fminf(vmin, __shfl_xor_sync(0xffffffffu, vmin, off));
    }
    __shared__ float smax[8], smin[8];
    int wid = threadIdx.x >> 5, lane = threadIdx.x & 31;
    if (lane == 0) { smax[wid] = vmax; smin[wid] = vmin; }
    __syncthreads();
    if (threadIdx.x == 0) {
        float bm = smax[0], bn = smin[0];
        #pragma unroll
        for (int i = 1; i < 8; i++) {
            bm = fmaxf(bm, smax[i]);
            bn = fminf(bn, smin[i]);
        }
        g_blkred[blockIdx.x] = make_float2(bm, bn);
    }
}

// ---------------- kernel: merge W = quant_w + left @ right -> fp16 (smem-tiled) ------
// grid (K_DIM/96, N_DIM/64) = (12, 18), 256 threads.
#define MKT 96
#define MNT 64
__global__ __launch_bounds__(256)
void merge_kernel(const float* __restrict__ qw,
                  const float* __restrict__ rw,
                  const float* __restrict__ lw) {
    __shared__ float lw_s[MNT][R_DIM + 4];   // 64 x 68
    __shared__ float rw_s[R_DIM][MKT];       // 64 x 96

    const int k0 = blockIdx.x * MKT;
    const int n0 = blockIdx.y * MNT;
    const int tid = threadIdx.x;

    for (int i = tid; i < MNT * R_DIM; i += 256) {
        int n = i >> 6, r = i & 63;
        lw_s[n][r] = lw[(n0 + n) * R_DIM + r];
    }
    for (int i = tid; i < R_DIM * MKT; i += 256) {
        int r = i / MKT, k = i - r * MKT;
        rw_s[r][k] = rw[r * K_DIM + k0 + k];
    }
    __syncthreads();

    const int nl = tid >> 3;            // 0..31
    const int kl = tid & 7;             // k = kl + 8*j, j = 0..11

    float acc0[12], acc1[12];
    #pragma unroll
    for (int j = 0; j < 12; j++) {
        acc0[j] = qw[(size_t)(n0 + nl) * K_DIM + k0 + kl + 8 * j];
        acc1[j] = qw[(size_t)(n0 + nl + 32) * K_DIM + k0 + kl + 8 * j];
    }
    #pragma unroll 4
    for (int r = 0; r < R_DIM; r++) {
        float l0 = lw_s[nl][r];
        float l1 = lw_s[nl + 32][r];
        #pragma unroll
        for (int j = 0; j < 12; j++) {
            float rv = rw_s[r][kl + 8 * j];
            acc0[j] = fmaf(l0, rv, acc0[j]);
            acc1[j] = fmaf(l1, rv, acc1[j]);
        }
    }
    #pragma unroll
    for (int j = 0; j < 12; j++) {
        g_W[(size_t)(n0 + nl) * K_DIM + k0 + kl + 8 * j] = __float2half_rn(acc0[j]);
        g_W[(size_t)(n0 + nl + 32) * K_DIM + k0 + kl + 8 * j] = __float2half_rn(acc1[j]);
    }
}

// ---------------- kernel: finalize params + quantize A (fp16 output) ----------------
__global__ __launch_bounds__(256)
void quant_kernel(const float* __restrict__ x, const float* __restrict__ scales) {
    __shared__ float4 rinv4[K_DIM / 4];
    __shared__ float smax[8], smin[8];
    __shared__ float s_zp, s_rqs;

    {
        float* rinv = reinterpret_cast<float*>(rinv4);
        for (int k = threadIdx.x; k < K_DIM; k += 256)
            rinv[k] = 1.0f / scales[k];
    }

    const float INF = __int_as_float(0x7f800000);
    float vmax = -INF, vmin = INF;
    for (int i = threadIdx.x; i < RBLOCKS; i += 256) {
        float2 t = g_blkred[i];
        vmax = fmaxf(vmax, t.x);
        vmin = fminf(vmin, t.y);
    }
    #pragma unroll
    for (int off = 16; off > 0; off >>= 1) {
        vmax = fmaxf(vmax, __shfl_xor_sync(0xffffffffu, vmax, off));
        vmin = fminf(vmin, __shfl_xor_sync(0xffffffffu, vmin, off));
    }
    int wid = threadIdx.x >> 5, lane = threadIdx.x & 31;
    if (lane == 0) { smax[wid] = vmax; smin[wid] = vmin; }
    __syncthreads();
    if (threadIdx.x == 0) {
        float mx = smax[0], mn = smin[0];
        #pragma unroll
        for (int i = 1; i < 8; i++) {
            mx = fmaxf(mx, smax[i]);
            mn = fminf(mn, smin[i]);
        }
        float qs = (mx - mn) / QMAXV;
        s_zp = rintf(-mn / qs);
        s_rqs = 1.0f / qs;
        if (blockIdx.x == 0) g_scale = qs;
    }
    __syncthreads();
    const float zp = s_zp, rqs = s_rqs;

    const int total8 = (M_DIM * K_DIM) / 8;
    const int stride = 1152 * 256;
    for (int v = blockIdx.x * 256 + threadIdx.x; v < total8; v += stride) {
        float4 x0 = reinterpret_cast<const float4*>(x)[2 * v];
        float4 x1 = reinterpret_cast<const float4*>(x)[2 * v + 1];
        int ri = (2 * v) % (K_DIM / 4);
        float4 r0 = rinv4[ri];
        float4 r1 = rinv4[ri + 1];
        float f[8];
        f[0] = x0.x * r0.x; f[1] = x0.y * r0.y;
        f[2] = x0.z * r0.z; f[3] = x0.w * r0.w;
        f[4] = x1.x * r1.x; f[5] = x1.y * r1.y;
        f[6] = x1.z * r1.z; f[7] = x1.w * r1.w;
        #pragma unroll
        for (int j = 0; j < 8; j++)
            f[j] = fminf(fmaxf(rintf(f[j] * rqs) + zp, 0.0f), QMAXV) - zp;
        __half2 p0 = __floats2half2_rn(f[0], f[1]);
        __half2 p1 = __floats2half2_rn(f[2], f[3]);
        __half2 p2 = __floats2half2_rn(f[4], f[5]);
        __half2 p3 = __floats2half2_rn(f[6], f[7]);
        uint4 u;
        u.x = *reinterpret_cast<unsigned*>(&p0);
        u.y = *reinterpret_cast<unsigned*>(&p1);
        u.z = *reinterpret_cast<unsigned*>(&p2);
        u.w = *reinterpret_cast<unsigned*>(&p3);
        reinterpret_cast<uint4*>(g_A)[v] = u;
    }
}

// ---------------- kernel: fp16 mma.sync GEMM (R13 shape), out = s*(A@W^T)+bias -------
// CTA tile 128x128, 256 threads, 8 warps as 2(M) x 4(N), warp tile 64x32.
// 2 CTAs per SM (4 warps/SMSP), no spills.
#define BM 128
#define BN 128
#define BK 64
#define NSTAGES 3
#define KITERS (K_DIM / BK)             // 18
#define PADH 72
#define PADB (PADH * 2)                 // 144 bytes/row
#define TILE_B (128 * PADB)             // 18432
#define STAGE_B (2 * TILE_B)            // 36864
#define SMEM_DYN (NSTAGES * STAGE_B)    // 110592 per CTA (x2 = 221184 <= 227KB)

__device__ __forceinline__ void ldm_x4(uint32_t* d, uint32_t addr) {
    asm volatile("ldmatrix.sync.aligned.m8n8.x4.shared.b16 {%0,%1,%2,%3}, [%4];"
                 : "=r"(d[0]), "=r"(d[1]), "=r"(d[2]), "=r"(d[3]) : "r"(addr));
}
__device__ __forceinline__ void hmma16816(float* c, const uint32_t* a, const uint32_t* b) {
    asm volatile(
        "mma.sync.aligned.m16n8k16.row.col.f32.f16.f16.f32 "
        "{%0,%1,%2,%3}, {%4,%5,%6,%7}, {%8,%9}, {%0,%1,%2,%3};\n"
        : "+f"(c[0]), "+f"(c[1]), "+f"(c[2]), "+f"(c[3])
        : "r"(a[0]), "r"(a[1]), "r"(a[2]), "r"(a[3]), "r"(b[0]), "r"(b[1]));
}

__device__ __forceinline__ void load_stage(uint32_t sA, uint32_t sB,
                                           const __half* Ag, const __half* Bg,
                                           int k0, int tid) {
    #pragma unroll
    for (int q = 0; q < 4; q++) {
        int c = q * 256 + tid;            // 0..1023
        int row = c >> 3;                 // 0..127
        int col16 = c & 7;
        uint32_t soff = (uint32_t)row * PADB + col16 * 16;
        CP_ASYNC16(sA + soff, Ag + (size_t)row * K_DIM + k0 + col16 * 8);
        CP_ASYNC16(sB + soff, Bg + (size_t)row * K_DIM + k0 + col16 * 8);
    }
}

__global__ __launch_bounds__(256, 2)
void gemm_kernel(const float* __restrict__ bias, float* __restrict__ out) {
    extern __shared__ char dsmem[];
    const uint32_t sbase = smem_u32(dsmem);

    const int tid = threadIdx.x;
    const int lane = tid & 31;
    const int warp = tid >> 5;
    const int warp_m = warp >> 2;   // 2 warp rows (64 rows each)
    const int warp_n = warp & 3;    // 4 warp cols (32 cols each)
    const int gid = lane >> 2;
    const int tig = lane & 3;

    const int m0 = blockIdx.y * BM;
    const int n0 = blockIdx.x * BN;
    const __half* Ag = g_A + (size_t)m0 * K_DIM;
    const __half* Bg = g_W + (size_t)n0 * K_DIM;

    float acc[4][4][4];
    #pragma unroll
    for (int i = 0; i < 4; i++)
        #pragma unroll
        for (int j = 0; j < 4; j++)
            #pragma unroll
            for (int r = 0; r < 4; r++) acc[i][j][r] = 0.0f;

    const int lane15 = lane & 15;
    const int laneHiA = (lane >> 4) * 16;
    const uint32_t aLaneOff = (uint32_t)(warp_m * 64 + lane15) * PADB + laneHiA;
    const int rowB = warp_n * 32 + (lane >> 4) * 8 + (lane & 7);
    const int kaddB = ((lane >> 3) & 1) * 16;
    const uint32_t bLaneOff = (uint32_t)rowB * PADB + kaddB;

    #pragma unroll
    for (int st = 0; st < NSTAGES - 1; st++) {
        const uint32_t sA = sbase + st * STAGE_B;
        load_stage(sA, sA + TILE_B, Ag, Bg, st * BK, tid);
        CP_COMMIT();
    }

    for (int it = 0; it < KITERS; ++it) {
        CP_WAIT1();
        __syncthreads();

        const int cbuf = it % NSTAGES;
        const uint32_t sA = sbase + cbuf * STAGE_B;
        const uint32_t sB = sA + TILE_B;

        const int itn = it + NSTAGES - 1;
        if (itn < KITERS) {
            const int fbuf = itn % NSTAGES;
            const uint32_t fA = sbase + fbuf * STAGE_B;
            load_stage(fA, fA + TILE_B, Ag, Bg, itn * BK, tid);
        }
        CP_COMMIT();

        #pragma unroll
        for (int ks = 0; ks < 4; ks++) {
            uint32_t a[4][4], b[2][4];
            #pragma unroll
            for (int im = 0; im < 4; im++)
                ldm_x4(a[im], sA + aLaneOff + (uint32_t)im * 16 * PADB + ks * 32);
            #pragma unroll
            for (int j2 = 0; j2 < 2; j2++)
                ldm_x4(b[j2], sB + bLaneOff + (uint32_t)j2 * 16 * PADB + ks * 32);
            #pragma unroll
            for (int im = 0; im < 4; im++) {
                hmma16816(acc[im][0], a[im], &b[0][0]);
                hmma16816(acc[im][1], a[im], &b[0][2]);
                hmma16816(acc[im][2], a[im], &b[1][0]);
                hmma16816(acc[im][3], a[im], &b[1][2]);
            }
        }
    }

    const float s = g_scale;
    #pragma unroll
    for (int im = 0; im < 4; im++) {
        int m = m0 + warp_m * 64 + im * 16 + gid;
        #pragma unroll
        for (int jn = 0; jn < 4; jn++) {
            int n = n0 + warp_n * 32 + jn * 8 + tig * 2;
            float b0 = bias[n], b1 = bias[n + 1];
            float2 v0, v1;
            v0.x = acc[im][jn][0] * s + b0;
            v0.y = acc[im][jn][1] * s + b1;
            v1.x = acc[im][jn][2] * s + b0;
            v1.y = acc[im][jn][3] * s + b1;
            *reinterpret_cast<float2*>(out + (size_t)m * N_DIM + n) = v0;
            *reinterpret_cast<float2*>(out + (size_t)(m + 8) * N_DIM + n) = v1;
        }
    }
}

// ---------------- launch ----------------
extern "C" void kernel_launch(void* const* d_in, const int* in_sizes, int n_in,
                              void* d_out, int out_size) {
    const float* x      = (const float*)d_in[0];
    const float* qw     = (const float*)d_in[1];
    const float* rw     = (const float*)d_in[2];
    const float* lw     = (const float*)d_in[3];
    const float* bias   = (const float*)d_in[4];
    const float* scales = (const float*)d_in[5];
    float* out = (float*)d_out;

    static cudaStream_t s2 = nullptr;
    static cudaEvent_t ev_fork = nullptr, ev_join = nullptr;
    static bool init_done = false;
    if (!init_done) {
        cudaFuncSetAttribute(gemm_kernel, cudaFuncAttributeMaxDynamicSharedMemorySize, SMEM_DYN);
        cudaStreamCreateWithFlags(&s2, cudaStreamNonBlocking);
        cudaEventCreateWithFlags(&ev_fork, cudaEventDisableTiming);
        cudaEventCreateWithFlags(&ev_join, cudaEventDisableTiming);
        init_done = true;
    }

    // fork: merge (independent, cheap) on s2, overlapping reduce+quant
    cudaEventRecord(ev_fork, 0);
    cudaStreamWaitEvent(s2, ev_fork, 0);
    merge_kernel<<<dim3(K_DIM / MKT, N_DIM / MNT), 256, 0, s2>>>(qw, rw, lw);
    cudaEventRecord(ev_join, s2);

    // main chain: reduce -> quant (finalizes params) -> gemm
    reduce_kernel<<<RBLOCKS, 256>>>(x, scales);
    quant_kernel<<<1152, 256>>>(x, scales);
    cudaStreamWaitEvent(0, ev_join, 0);
    gemm_kernel<<<dim3(N_DIM / BN, M_DIM / BM), 256, SMEM_DYN>>>(bias, out);
}

// round 16
// speedup vs baseline: 1.1603x; 1.0979x over previous
#include <cuda_runtime.h>
#include <cuda_fp16.h>
#include <cstdint>

// Problem dims (fixed by the dataset)
#define M_DIM 32768   // B*S
#define K_DIM 1152
#define N_DIM 1152
#define R_DIM 64
#define QMAXV 255.0f
#define RBLOCKS 2304                      // reduce grid size

// ---------------- device scratch ----------------
__device__ float2   g_blkred[RBLOCKS];    // per-block (max, min); fully rewritten each call
__device__ float    g_scale;              // published by quant block 0
__device__ __align__(16) __half g_A[(size_t)M_DIM * K_DIM];  // (q-zp): exact int in fp16
__device__ __align__(16) __half g_W[(size_t)N_DIM * K_DIM];  // merged weight in fp16

__device__ __forceinline__ uint32_t smem_u32(const void* p) {
    uint32_t a;
    asm("{ .reg .u64 t; cvta.to.shared.u64 t, %1; cvt.u32.u64 %0, t; }" : "=r"(a) : "l"(p));
    return a;
}

#define CP_ASYNC16(saddr, gptr) \
    asm volatile("cp.async.cg.shared.global [%0], [%1], 16;" :: "r"(saddr), "l"(gptr) : "memory")
#define CP_COMMIT() asm volatile("cp.async.commit_group;" ::: "memory")
#define CP_WAIT1()  asm volatile("cp.async.wait_group 1;" ::: "memory")

// ---------------- kernel: per-block min/max of x*rinv ----------------
__global__ __launch_bounds__(256)
void reduce_kernel(const float* __restrict__ x, const float* __restrict__ scales) {
    __shared__ float4 rinv4[K_DIM / 4];
    {
        float* rinv = reinterpret_cast<float*>(rinv4);
        for (int k = threadIdx.x; k < K_DIM; k += 256)
            rinv[k] = 1.0f / scales[k];
    }
    __syncthreads();

    const int total4 = (M_DIM * K_DIM) / 4;
    const float INF = __int_as_float(0x7f800000);
    float vmax = -INF, vmin = INF;
    for (int v = blockIdx.x * 256 + threadIdx.x; v < total4; v += RBLOCKS * 256) {
        float4 xv = reinterpret_cast<const float4*>(x)[v];
        float4 rv = rinv4[v % (K_DIM / 4)];
        float a = xv.x * rv.x;
        float b = xv.y * rv.y;
        float c = xv.z * rv.z;
        float d = xv.w * rv.w;
        vmax = fmaxf(vmax, fmaxf(fmaxf(a, b), fmaxf(c, d)));
        vmin = fminf(vmin, fminf(fminf(a, b), fminf(c, d)));
    }
    #pragma unroll
    for (int off = 16; off > 0; off >>= 1) {
        vmax = fmaxf(vmax, __shfl_xor_sync(0xffffffffu, vmax, off));
        vmin = fminf(vmin, __shfl_xor_sync(0xffffffffu, vmin, off));
    }
    __shared__ float smax[8], smin[8];
    int wid = threadIdx.x >> 5, lane = threadIdx.x & 31;
    if (lane == 0) { smax[wid] = vmax; smin[wid] = vmin; }
    __syncthreads();
    if (threadIdx.x == 0) {
        float bm = smax[0], bn = smin[0];
        #pragma unroll
        for (int i = 1; i < 8; i++) {
            bm = fmaxf(bm, smax[i]);
            bn = fminf(bn, smin[i]);
        }
        g_blkred[blockIdx.x] = make_float2(bm, bn);
    }
}

// ---------------- kernel: merge W = quant_w + left @ right -> fp16 (smem-tiled) ------
#define MKT 96
#define MNT 64
__global__ __launch_bounds__(256)
void merge_kernel(const float* __restrict__ qw,
                  const float* __restrict__ rw,
                  const float* __restrict__ lw) {
    __shared__ float lw_s[MNT][R_DIM + 4];
    __shared__ float rw_s[R_DIM][MKT];

    const int k0 = blockIdx.x * MKT;
    const int n0 = blockIdx.y * MNT;
    const int tid = threadIdx.x;

    for (int i = tid; i < MNT * R_DIM; i += 256) {
        int n = i >> 6, r = i & 63;
        lw_s[n][r] = lw[(n0 + n) * R_DIM + r];
    }
    for (int i = tid; i < R_DIM * MKT; i += 256) {
        int r = i / MKT, k = i - r * MKT;
        rw_s[r][k] = rw[r * K_DIM + k0 + k];
    }
    __syncthreads();

    const int nl = tid >> 3;
    const int kl = tid & 7;

    float acc0[12], acc1[12];
    #pragma unroll
    for (int j = 0; j < 12; j++) {
        acc0[j] = qw[(size_t)(n0 + nl) * K_DIM + k0 + kl + 8 * j];
        acc1[j] = qw[(size_t)(n0 + nl + 32) * K_DIM + k0 + kl + 8 * j];
    }
    #pragma unroll 4
    for (int r = 0; r < R_DIM; r++) {
        float l0 = lw_s[nl][r];
        float l1 = lw_s[nl + 32][r];
        #pragma unroll
        for (int j = 0; j < 12; j++) {
            float rv = rw_s[r][kl + 8 * j];
            acc0[j] = fmaf(l0, rv, acc0[j]);
            acc1[j] = fmaf(l1, rv, acc1[j]);
        }
    }
    #pragma unroll
    for (int j = 0; j < 12; j++) {
        g_W[(size_t)(n0 + nl) * K_DIM + k0 + kl + 8 * j] = __float2half_rn(acc0[j]);
        g_W[(size_t)(n0 + nl + 32) * K_DIM + k0 + kl + 8 * j] = __float2half_rn(acc1[j]);
    }
}

// ---------------- kernel: finalize params + quantize A (fp16 output) ----------------
__global__ __launch_bounds__(256)
void quant_kernel(const float* __restrict__ x, const float* __restrict__ scales) {
    __shared__ float4 rinv4[K_DIM / 4];
    __shared__ float smax[8], smin[8];
    __shared__ float s_zp, s_rqs;

    {
        float* rinv = reinterpret_cast<float*>(rinv4);
        for (int k = threadIdx.x; k < K_DIM; k += 256)
            rinv[k] = 1.0f / scales[k];
    }

    const float INF = __int_as_float(0x7f800000);
    float vmax = -INF, vmin = INF;
    for (int i = threadIdx.x; i < RBLOCKS; i += 256) {
        float2 t = g_blkred[i];
        vmax = fmaxf(vmax, t.x);
        vmin = fminf(vmin, t.y);
    }
    #pragma unroll
    for (int off = 16; off > 0; off >>= 1) {
        vmax = fmaxf(vmax, __shfl_xor_sync(0xffffffffu, vmax, off));
        vmin = fminf(vmin, __shfl_xor_sync(0xffffffffu, vmin, off));
    }
    int wid = threadIdx.x >> 5, lane = threadIdx.x & 31;
    if (lane == 0) { smax[wid] = vmax; smin[wid] = vmin; }
    __syncthreads();
    if (threadIdx.x == 0) {
        float mx = smax[0], mn = smin[0];
        #pragma unroll
        for (int i = 1; i < 8; i++) {
            mx = fmaxf(mx, smax[i]);
            mn = fminf(mn, smin[i]);
        }
        float qs = (mx - mn) / QMAXV;
        s_zp = rintf(-mn / qs);
        s_rqs = 1.0f / qs;
        if (blockIdx.x == 0) g_scale = qs;
    }
    __syncthreads();
    const float zp = s_zp, rqs = s_rqs;

    const int total8 = (M_DIM * K_DIM) / 8;
    const int stride = 1152 * 256;
    for (int v = blockIdx.x * 256 + threadIdx.x; v < total8; v += stride) {
        float4 x0 = reinterpret_cast<const float4*>(x)[2 * v];
        float4 x1 = reinterpret_cast<const float4*>(x)[2 * v + 1];
        int ri = (2 * v) % (K_DIM / 4);
        float4 r0 = rinv4[ri];
        float4 r1 = rinv4[ri + 1];
        float f[8];
        f[0] = x0.x * r0.x; f[1] = x0.y * r0.y;
        f[2] = x0.z * r0.z; f[3] = x0.w * r0.w;
        f[4] = x1.x * r1.x; f[5] = x1.y * r1.y;
        f[6] = x1.z * r1.z; f[7] = x1.w * r1.w;
        #pragma unroll
        for (int j = 0; j < 8; j++)
            f[j] = fminf(fmaxf(rintf(f[j] * rqs) + zp, 0.0f), QMAXV) - zp;
        __half2 p0 = __floats2half2_rn(f[0], f[1]);
        __half2 p1 = __floats2half2_rn(f[2], f[3]);
        __half2 p2 = __floats2half2_rn(f[4], f[5]);
        __half2 p3 = __floats2half2_rn(f[6], f[7]);
        uint4 u;
        u.x = *reinterpret_cast<unsigned*>(&p0);
        u.y = *reinterpret_cast<unsigned*>(&p1);
        u.z = *reinterpret_cast<unsigned*>(&p2);
        u.w = *reinterpret_cast<unsigned*>(&p3);
        reinterpret_cast<uint4*>(g_A)[v] = u;
    }
}

// ---------------- kernel: fp16 mma.sync GEMM, out = s*(A@W^T)+bias ----------------
// CTA tile 128x128, 256 threads, 8 warps as 2(M) x 4(N), warp tile 64x32.
// 2 CTAs per SM (4 warps/SMSP).
#define BM 128
#define BN 128
#define BK 64
#define NSTAGES 3
#define KITERS (K_DIM / BK)             // 18
#define PADH 72
#define PADB (PADH * 2)                 // 144 bytes/row
#define TILE_B (128 * PADB)             // 18432
#define STAGE_B (2 * TILE_B)            // 36864
#define SMEM_DYN (NSTAGES * STAGE_B)    // 110592 per CTA (x2 = 221184 <= 227KB)

__device__ __forceinline__ void ldm_x4(uint32_t* d, uint32_t addr) {
    asm volatile("ldmatrix.sync.aligned.m8n8.x4.shared.b16 {%0,%1,%2,%3}, [%4];"
                 : "=r"(d[0]), "=r"(d[1]), "=r"(d[2]), "=r"(d[3]) : "r"(addr));
}
__device__ __forceinline__ void hmma16816(float* c, const uint32_t* a, const uint32_t* b) {
    asm volatile(
        "mma.sync.aligned.m16n8k16.row.col.f32.f16.f16.f32 "
        "{%0,%1,%2,%3}, {%4,%5,%6,%7}, {%8,%9}, {%0,%1,%2,%3};\n"
        : "+f"(c[0]), "+f"(c[1]), "+f"(c[2]), "+f"(c[3])
        : "r"(a[0]), "r"(a[1]), "r"(a[2]), "r"(a[3]), "r"(b[0]), "r"(b[1]));
}

__global__ __launch_bounds__(256, 2)
void gemm_kernel(const float* __restrict__ bias, float* __restrict__ out) {
    extern __shared__ char dsmem[];
    const uint32_t sbase = smem_u32(dsmem);

    const int tid = threadIdx.x;
    const int lane = tid & 31;
    const int warp = tid >> 5;
    const int warp_m = warp >> 2;   // 2 warp rows (64 rows each)
    const int warp_n = warp & 3;    // 4 warp cols (32 cols each)
    const int gid = lane >> 2;
    const int tig = lane & 3;

    const int m0 = blockIdx.y * BM;
    const int n0 = blockIdx.x * BN;
    const __half* Ag = g_A + (size_t)m0 * K_DIM;
    const __half* Bg = g_W + (size_t)n0 * K_DIM;

    // hoisted loader address math (constant per thread)
    uint32_t soff[4];
    size_t   goff[4];
    #pragma unroll
    for (int q = 0; q < 4; q++) {
        int c = q * 256 + tid;            // 0..1023
        int row = c >> 3;                 // 0..127
        int col16 = c & 7;                // 0..7
        soff[q] = (uint32_t)row * PADB + col16 * 16;
        goff[q] = (size_t)row * K_DIM + col16 * 8;
    }

    // prefetch bias values for this thread's epilogue columns
    float bias_r[8];
    #pragma unroll
    for (int jn = 0; jn < 4; jn++) {
        int n = n0 + warp_n * 32 + jn * 8 + tig * 2;
        bias_r[2 * jn]     = bias[n];
        bias_r[2 * jn + 1] = bias[n + 1];
    }

    float acc[4][4][4];
    #pragma unroll
    for (int i = 0; i < 4; i++)
        #pragma unroll
        for (int j = 0; j < 4; j++)
            #pragma unroll
            for (int r = 0; r < 4; r++) acc[i][j][r] = 0.0f;

    const int lane15 = lane & 15;
    const int laneHiA = (lane >> 4) * 16;
    const uint32_t aLaneOff = (uint32_t)(warp_m * 64 + lane15) * PADB + laneHiA;
    const int rowB = warp_n * 32 + (lane >> 4) * 8 + (lane & 7);
    const int kaddB = ((lane >> 3) & 1) * 16;
    const uint32_t bLaneOff = (uint32_t)rowB * PADB + kaddB;

    // prologue: prefetch stages 0,1
    #pragma unroll
    for (int st = 0; st < NSTAGES - 1; st++) {
        const uint32_t sA = sbase + st * STAGE_B;
        const uint32_t sB = sA + TILE_B;
        const int k0 = st * BK;
        #pragma unroll
        for (int q = 0; q < 4; q++) {
            CP_ASYNC16(sA + soff[q], Ag + goff[q] + k0);
            CP_ASYNC16(sB + soff[q], Bg + goff[q] + k0);
        }
        CP_COMMIT();
    }

    int cbuf = 0;                    // rotating buffer index (no modulo)
    int fbuf = NSTAGES - 1;          // buffer to fill (2 stages ahead)
    for (int it = 0; it < KITERS; ++it) {
        CP_WAIT1();
        __syncthreads();

        const uint32_t sA = sbase + cbuf * STAGE_B;
        const uint32_t sB = sA + TILE_B;
        const int itn = it + NSTAGES - 1;
        const bool do_pf = (itn < KITERS);
        const uint32_t fA = sbase + fbuf * STAGE_B;
        const uint32_t fB = fA + TILE_B;
        const int kpf = itn * BK;

        // ks = 0: fragments first, then half the prefetch
        {
            uint32_t a[4][4], b[2][4];
            #pragma unroll
            for (int im = 0; im < 4; im++)
                ldm_x4(a[im], sA + aLaneOff + (uint32_t)im * 16 * PADB);
            #pragma unroll
            for (int j2 = 0; j2 < 2; j2++)
                ldm_x4(b[j2], sB + bLaneOff + (uint32_t)j2 * 16 * PADB);
            if (do_pf) {
                #pragma unroll
                for (int q = 0; q < 4; q++)
                    CP_ASYNC16(fA + soff[q], Ag + goff[q] + kpf);
            }
            #pragma unroll
            for (int im = 0; im < 4; im++) {
                hmma16816(acc[im][0], a[im], &b[0][0]);
                hmma16816(acc[im][1], a[im], &b[0][2]);
                hmma16816(acc[im][2], a[im], &b[1][0]);
                hmma16816(acc[im][3], a[im], &b[1][2]);
            }
        }
        // ks = 1: fragments, then the other half of the prefetch
        {
            uint32_t a[4][4], b[2][4];
            #pragma unroll
            for (int im = 0; im < 4; im++)
                ldm_x4(a[im], sA + aLaneOff + (uint32_t)im * 16 * PADB + 32);
            #pragma unroll
            for (int j2 = 0; j2 < 2; j2++)
                ldm_x4(b[j2], sB + bLaneOff + (uint32_t)j2 * 16 * PADB + 32);
            if (do_pf) {
                #pragma unroll
                for (int q = 0; q < 4; q++)
                    CP_ASYNC16(fB + soff[q], Bg + goff[q] + kpf);
            }
            #pragma unroll
            for (int im = 0; im < 4; im++) {
                hmma16816(acc[im][0], a[im], &b[0][0]);
                hmma16816(acc[im][1], a[im], &b[0][2]);
                hmma16816(acc[im][2], a[im], &b[1][0]);
                hmma16816(acc[im][3], a[im], &b[1][2]);
            }
        }
        CP_COMMIT();
        // ks = 2, 3
        #pragma unroll
        for (int ks = 2; ks < 4; ks++) {
            uint32_t a[4][4], b[2][4];
            #pragma unroll
            for (int im = 0; im < 4; im++)
                ldm_x4(a[im], sA + aLaneOff + (uint32_t)im * 16 * PADB + ks * 32);
            #pragma unroll
            for (int j2 = 0; j2 < 2; j2++)
                ldm_x4(b[j2], sB + bLaneOff + (uint32_t)j2 * 16 * PADB + ks * 32);
            #pragma unroll
            for (int im = 0; im < 4; im++) {
                hmma16816(acc[im][0], a[im], &b[0][0]);
                hmma16816(acc[im][1], a[im], &b[0][2]);
                hmma16816(acc[im][2], a[im], &b[1][0]);
                hmma16816(acc[im][3], a[im], &b[1][2]);
            }
        }

        cbuf = (cbuf == NSTAGES - 1) ? 0 : cbuf + 1;
        fbuf = (fbuf == NSTAGES - 1) ? 0 : fbuf + 1;
    }

    const float s = g_scale;
    #pragma unroll
    for (int im = 0; im < 4; im++) {
        int m = m0 + warp_m * 64 + im * 16 + gid;
        #pragma unroll
        for (int jn = 0; jn < 4; jn++) {
            int n = n0 + warp_n * 32 + jn * 8 + tig * 2;
            float2 v0, v1;
            v0.x = acc[im][jn][0] * s + bias_r[2 * jn];
            v0.y = acc[im][jn][1] * s + bias_r[2 * jn + 1];
            v1.x = acc[im][jn][2] * s + bias_r[2 * jn];
            v1.y = acc[im][jn][3] * s + bias_r[2 * jn + 1];
            *reinterpret_cast<float2*>(out + (size_t)m * N_DIM + n) = v0;
            *reinterpret_cast<float2*>(out + (size_t)(m + 8) * N_DIM + n) = v1;
        }
    }
}

// ---------------- launch ----------------
extern "C" void kernel_launch(void* const* d_in, const int* in_sizes, int n_in,
                              void* d_out, int out_size) {
    const float* x      = (const float*)d_in[0];
    const float* qw     = (const float*)d_in[1];
    const float* rw     = (const float*)d_in[2];
    const float* lw     = (const float*)d_in[3];
    const float* bias   = (const float*)d_in[4];
    const float* scales = (const float*)d_in[5];
    float* out = (float*)d_out;

    static cudaStream_t s2 = nullptr;
    static cudaEvent_t ev_fork = nullptr, ev_join = nullptr;
    static bool init_done = false;
    if (!init_done) {
        cudaFuncSetAttribute(gemm_kernel, cudaFuncAttributeMaxDynamicSharedMemorySize, SMEM_DYN);
        cudaStreamCreateWithFlags(&s2, cudaStreamNonBlocking);
        cudaEventCreateWithFlags(&ev_fork, cudaEventDisableTiming);
        cudaEventCreateWithFlags(&ev_join, cudaEventDisableTiming);
        init_done = true;
    }

    // fork: merge (independent, cheap) on s2, overlapping reduce+quant
    cudaEventRecord(ev_fork, 0);
    cudaStreamWaitEvent(s2, ev_fork, 0);
    merge_kernel<<<dim3(K_DIM / MKT, N_DIM / MNT), 256, 0, s2>>>(qw, rw, lw);
    cudaEventRecord(ev_join, s2);

    // main chain: reduce -> quant (finalizes params) -> gemm
    reduce_kernel<<<RBLOCKS, 256>>>(x, scales);
    quant_kernel<<<1152, 256>>>(x, scales);
    cudaStreamWaitEvent(0, ev_join, 0);
    gemm_kernel<<<dim3(N_DIM / BN, M_DIM / BM), 256, SMEM_DYN>>>(bias, out);
}